// round 11
// baseline (speedup 1.0000x reference)
#include <cuda_runtime.h>
#include <cstdint>

// z = sum_{p,q,r} C[p*9+q*3+r] * u0_p * u1_q * u2_r,  u_i = (1, cos x_i, sin x_i)
//
// Fully fused, barrier-free kernel:
//   1. each thread front-batches its 8 input loads (in flight for ~1000 cyc)
//   2. EVERY WARP independently rebuilds the 27 trilinear coefficients from
//      q_weights using only registers + __shfl_sync (~600-1000 cyc) — fully
//      hidden under its own loads' DRAM latency. The final __shfl_xor tree
//      reduction leaves all 27 coefficients in every lane.
//   3. evaluate. No shared memory, no __syncthreads, no second kernel.

static constexpr int SPT = 8;
static constexpr int BLOCK = 256;

__global__ void __launch_bounds__(BLOCK) vqc_fused(const float4* __restrict__ in,
                                                   float* __restrict__ out,
                                                   const float* __restrict__ qw,
                                                   int B) {
    const unsigned FULL = 0xFFFFFFFFu;
    const int t = threadIdx.x;
    const int lane = t & 31;
    const int T = gridDim.x * BLOCK;
    const int gidx = blockIdx.x * BLOCK + t;

    // ---- 1. Front-batch ALL input loads ------------------------------------
    float4 x[SPT];
    #pragma unroll
    for (int k = 0; k < SPT; k++) {
        int i = gidx + k * T;
        i = (i < B) ? i : (B - 1);
        x[k] = in[(size_t)i * 2];        // first 16B of the 32B row
    }

    // ---- 2. Per-warp coefficient build (registers + shfl only) -------------
    // Parallel sincos of all 18 half-angles (lanes 0..17), broadcast via shfl.
    float ang = (lane < 18) ? 0.5f * qw[lane] : 0.f;
    float sh, ch;
    __sincosf(ang, &sh, &ch);

    // Lanes 0..7 simulate basis column j = lane&7 of the fixed unitary.
    const int j = lane & 7;
    float sr[8], si[8];
    #pragma unroll
    for (int m = 0; m < 8; m++) { sr[m] = 0.f; si[m] = 0.f; }
    sr[j] = 1.0f;

    #pragma unroll
    for (int g = 0; g < 9; g++) {        // layer = g/3, qubit = g%3
        const int bit = 4 >> (g % 3);
        float cy = __shfl_sync(FULL, ch, 2 * g);
        float sy = __shfl_sync(FULL, sh, 2 * g);
        float cz = __shfl_sync(FULL, ch, 2 * g + 1);
        float sz = __shfl_sync(FULL, sh, 2 * g + 1);

        // RY
        #pragma unroll
        for (int m = 0; m < 8; m++) {
            if (m & bit) continue;
            int m1 = m | bit;
            float ar = sr[m],  ai = si[m];
            float br = sr[m1], bi = si[m1];
            sr[m]  = cy * ar - sy * br;  si[m]  = cy * ai - sy * bi;
            sr[m1] = sy * ar + cy * br;  si[m1] = sy * ai + cy * bi;
        }
        // RZ
        #pragma unroll
        for (int m = 0; m < 8; m++) {
            float ar = sr[m], ai = si[m];
            if (m & bit) { sr[m] = cz * ar - sz * ai; si[m] = cz * ai + sz * ar; }
            else         { sr[m] = cz * ar + sz * ai; si[m] = cz * ai - sz * ar; }
        }
        // End of layer: CNOT01 then CNOT12
        if (g % 3 == 2) {
            #pragma unroll
            for (int m = 4; m < 6; m++) {    // swap (4,6),(5,7)
                int m1 = m | 2; float tmp;
                tmp = sr[m]; sr[m] = sr[m1]; sr[m1] = tmp;
                tmp = si[m]; si[m] = si[m1]; si[m1] = tmp;
            }
            #pragma unroll
            for (int m = 2; m < 8; m += 4) { // swap (2,3),(6,7)
                int m1 = m | 1; float tmp;
                tmp = sr[m]; sr[m] = sr[m1]; sr[m1] = tmp;
                tmp = si[m]; si[m] = si[m1]; si[m1] = tmp;
            }
        }
    }
    // Lanes 8..31 hold garbage columns (j = lane&7 duplicates) — only lanes
    // 0..7 are ever read below via shfl.

    // A-entries: this lane owns entries e = lane and e + 32 of the 8x8 A.
    // A[jj][kk] = sum_m sign(m) (U[m][jj].re*U[m][kk].re + U[m][jj].im*U[m][kk].im)
    const int jj1 = lane >> 3,        kk = lane & 7;
    const int jj2 = 4 + (lane >> 3);  // (lane+32)>>3 ; kk identical
    float a1 = 0.f, a2 = 0.f;
    #pragma unroll
    for (int m = 0; m < 8; m++) {
        float sgn = (m & 4) ? -1.f : 1.f;
        float urk = __shfl_sync(FULL, sr[m], kk);
        float uik = __shfl_sync(FULL, si[m], kk);
        float urj1 = __shfl_sync(FULL, sr[m], jj1);
        float uij1 = __shfl_sync(FULL, si[m], jj1);
        float urj2 = __shfl_sync(FULL, sr[m], jj2);
        float uij2 = __shfl_sync(FULL, si[m], jj2);
        a1 = fmaf(sgn, urj1 * urk + uij1 * uik, a1);
        a2 = fmaf(sgn, urj2 * urk + uij2 * uik, a2);
    }

    // Contraction: rank-1 contributions of entries (jj1,kk) and (jj2,kk)
    // into cpart[27], then 5-level xor tree -> all lanes hold the full C.
    float cpart[27];
    #pragma unroll
    for (int i = 0; i < 27; i++) cpart[i] = 0.f;

    #pragma unroll
    for (int h = 0; h < 2; h++) {
        int jjv = h ? jj2 : jj1;
        float a = h ? a2 : a1;

        float ga[3], gb[3], gc[3];
        {
            int aa = (jjv >> 2) & 1, bb = (kk >> 2) & 1;
            ga[0] = (aa == bb) ? 0.5f : 0.f;
            ga[1] = (aa == bb) ? (aa ? -0.5f : 0.5f) : 0.f;
            ga[2] = (aa != bb) ? 0.5f : 0.f;
        }
        {
            int aa = (jjv >> 1) & 1, bb = (kk >> 1) & 1;
            gb[0] = (aa == bb) ? 0.5f : 0.f;
            gb[1] = (aa == bb) ? (aa ? -0.5f : 0.5f) : 0.f;
            gb[2] = (aa != bb) ? 0.5f : 0.f;
        }
        {
            int aa = jjv & 1, bb = kk & 1;
            gc[0] = (aa == bb) ? 0.5f : 0.f;
            gc[1] = (aa == bb) ? (aa ? -0.5f : 0.5f) : 0.f;
            gc[2] = (aa != bb) ? 0.5f : 0.f;
        }

        #pragma unroll
        for (int p = 0; p < 3; p++) {
            float a0 = a * ga[p];
            #pragma unroll
            for (int q = 0; q < 3; q++) {
                float a01 = a0 * gb[q];
                #pragma unroll
                for (int r = 0; r < 3; r++)
                    cpart[p * 9 + q * 3 + r] =
                        fmaf(a01, gc[r], cpart[p * 9 + q * 3 + r]);
            }
        }
    }

    #pragma unroll
    for (int off = 16; off > 0; off >>= 1) {
        #pragma unroll
        for (int i = 0; i < 27; i++)
            cpart[i] += __shfl_xor_sync(FULL, cpart[i], off);
    }
    // cpart[] now holds the 27 coefficients in EVERY lane.

    // ---- 3. Evaluate SPT samples per thread --------------------------------
    #pragma unroll
    for (int k = 0; k < SPT; k++) {
        float C0, S0, C1, S1, C2, S2;
        __sincosf(x[k].x, &S0, &C0);
        __sincosf(x[k].y, &S1, &C1);
        __sincosf(x[k].z, &S2, &C2);

        float u0[3] = {1.f, C0, S0};
        float u1[3] = {1.f, C1, S1};
        float z = 0.f;
        #pragma unroll
        for (int p = 0; p < 3; p++) {
            #pragma unroll
            for (int q = 0; q < 3; q++) {
                const float* c3 = &cpart[p * 9 + q * 3];
                float w = c3[0];
                w = fmaf(c3[1], C2, w);
                w = fmaf(c3[2], S2, w);
                z = fmaf(u0[p] * u1[q], w, z);
            }
        }
        int i = gidx + k * T;
        if (i < B) out[i] = z;
    }
}

extern "C" void kernel_launch(void* const* d_in, const int* in_sizes, int n_in,
                              void* d_out, int out_size) {
    const float* inputs = (const float*)d_in[0];   // (B, 8) float32
    const float* qw     = (const float*)d_in[1];   // (3, 3, 2) float32
    float* out          = (float*)d_out;           // (B, 1) float32

    int B = in_sizes[0] / 8;
    int grid = (B + BLOCK * SPT - 1) / (BLOCK * SPT);   // 512 for B = 2^20

    vqc_fused<<<grid, BLOCK>>>((const float4*)inputs, out, qw, B);
}

// round 12
// speedup vs baseline: 1.1667x; 1.1667x over previous
#include <cuda_runtime.h>
#include <cstdint>

// z = sum_{p,q,r} C[p*9+q*3+r] * u0_p * u1_q * u2_r,  u_i = (1, cos x_i, sin x_i)
__device__ float d_C[27];

// ---------------------------------------------------------------------------
// Kernel 1: build the 27 trilinear coefficients from q_weights (18 floats).
// Single warp, no block barriers; all 18 sincos in parallel up front.
// ---------------------------------------------------------------------------
__global__ void build_coeffs(const float* __restrict__ qw) {
    __shared__ float Ure[8][8];   // [m][j]
    __shared__ float Uim[8][8];
    __shared__ float Aj[8][8];    // A[j][k]

    const unsigned FULL = 0xFFFFFFFFu;
    const int lane = threadIdx.x;

    float ang = (lane < 18) ? 0.5f * qw[lane] : 0.f;
    float sh, ch;
    __sincosf(ang, &sh, &ch);

    const int j = lane & 7;
    float sr[8], si[8];
    #pragma unroll
    for (int m = 0; m < 8; m++) { sr[m] = 0.f; si[m] = 0.f; }
    sr[j] = 1.0f;

    #pragma unroll
    for (int g = 0; g < 9; g++) {          // layer = g/3, qubit = g%3
        const int bit = 4 >> (g % 3);
        float cy = __shfl_sync(FULL, ch, 2 * g);
        float sy = __shfl_sync(FULL, sh, 2 * g);
        float cz = __shfl_sync(FULL, ch, 2 * g + 1);
        float sz = __shfl_sync(FULL, sh, 2 * g + 1);

        #pragma unroll
        for (int m = 0; m < 8; m++) {      // RY
            if (m & bit) continue;
            int m1 = m | bit;
            float ar = sr[m],  ai = si[m];
            float br = sr[m1], bi = si[m1];
            sr[m]  = cy * ar - sy * br;  si[m]  = cy * ai - sy * bi;
            sr[m1] = sy * ar + cy * br;  si[m1] = sy * ai + cy * bi;
        }
        #pragma unroll
        for (int m = 0; m < 8; m++) {      // RZ
            float ar = sr[m], ai = si[m];
            if (m & bit) { sr[m] = cz * ar - sz * ai; si[m] = cz * ai + sz * ar; }
            else         { sr[m] = cz * ar + sz * ai; si[m] = cz * ai - sz * ar; }
        }
        if (g % 3 == 2) {
            #pragma unroll
            for (int m = 4; m < 6; m++) {  // CNOT01: swap (4,6),(5,7)
                int m1 = m | 2; float tmp;
                tmp = sr[m]; sr[m] = sr[m1]; sr[m1] = tmp;
                tmp = si[m]; si[m] = si[m1]; si[m1] = tmp;
            }
            #pragma unroll
            for (int m = 2; m < 8; m += 4) { // CNOT12: swap (2,3),(6,7)
                int m1 = m | 1; float tmp;
                tmp = sr[m]; sr[m] = sr[m1]; sr[m1] = tmp;
                tmp = si[m]; si[m] = si[m1]; si[m1] = tmp;
            }
        }
    }

    if (lane < 8) {
        #pragma unroll
        for (int m = 0; m < 8; m++) { Ure[m][j] = sr[m]; Uim[m][j] = si[m]; }
    }
    __syncwarp();

    #pragma unroll
    for (int h = 0; h < 2; h++) {
        int e = lane + h * 32;
        int jj = e >> 3, kk = e & 7;
        float a = 0.f;
        #pragma unroll
        for (int m = 0; m < 8; m++) {
            float sgn = (m & 4) ? -1.f : 1.f;
            a += sgn * (Ure[m][jj] * Ure[m][kk] + Uim[m][jj] * Uim[m][kk]);
        }
        Aj[jj][kk] = a;
    }
    __syncwarp();

    float cpart[27];
    #pragma unroll
    for (int i = 0; i < 27; i++) cpart[i] = 0.f;

    #pragma unroll
    for (int h = 0; h < 2; h++) {
        int e = lane + h * 32;
        int jj = e >> 3, kk = e & 7;
        float a = Aj[jj][kk];

        float ga[3], gb[3], gc[3];
        {
            int aa = (jj >> 2) & 1, bb = (kk >> 2) & 1;
            ga[0] = (aa == bb) ? 0.5f : 0.f;
            ga[1] = (aa == bb) ? (aa ? -0.5f : 0.5f) : 0.f;
            ga[2] = (aa != bb) ? 0.5f : 0.f;
        }
        {
            int aa = (jj >> 1) & 1, bb = (kk >> 1) & 1;
            gb[0] = (aa == bb) ? 0.5f : 0.f;
            gb[1] = (aa == bb) ? (aa ? -0.5f : 0.5f) : 0.f;
            gb[2] = (aa != bb) ? 0.5f : 0.f;
        }
        {
            int aa = jj & 1, bb = kk & 1;
            gc[0] = (aa == bb) ? 0.5f : 0.f;
            gc[1] = (aa == bb) ? (aa ? -0.5f : 0.5f) : 0.f;
            gc[2] = (aa != bb) ? 0.5f : 0.f;
        }

        #pragma unroll
        for (int p = 0; p < 3; p++) {
            float a0 = a * ga[p];
            #pragma unroll
            for (int q = 0; q < 3; q++) {
                float a01 = a0 * gb[q];
                #pragma unroll
                for (int r = 0; r < 3; r++)
                    cpart[p * 9 + q * 3 + r] =
                        fmaf(a01, gc[r], cpart[p * 9 + q * 3 + r]);
            }
        }
    }

    #pragma unroll
    for (int off = 16; off > 0; off >>= 1) {
        #pragma unroll
        for (int i = 0; i < 27; i++)
            cpart[i] += __shfl_xor_sync(FULL, cpart[i], off);
    }
    if (lane < 27) d_C[lane] = cpart[lane];
}

// ---------------------------------------------------------------------------
// Kernel 2 (PDL): loads -> ALL sincos -> grid-dependency sync -> trilinear.
// Everything before the sync is independent of build_coeffs, so its whole
// execution (plus the DRAM latency of the loads) overlaps the build.
// ---------------------------------------------------------------------------
static constexpr int SPT = 8;
static constexpr int BLOCK = 256;

__global__ void __launch_bounds__(BLOCK) vqc_eval(const float4* __restrict__ in,
                                                  float* __restrict__ out, int B) {
    const int T = gridDim.x * BLOCK;
    const int t = blockIdx.x * BLOCK + threadIdx.x;

    // Front-batch ALL loads.
    float4 x[SPT];
    #pragma unroll
    for (int k = 0; k < SPT; k++) {
        int i = t + k * T;
        i = (i < B) ? i : (B - 1);
        x[k] = in[(size_t)i * 2];     // first 16B of the 32B row
    }

    // All trig BEFORE the dependency sync — overlaps build_coeffs.
    float C0[SPT], S0[SPT], C1[SPT], S1[SPT], C2[SPT], S2[SPT];
    #pragma unroll
    for (int k = 0; k < SPT; k++) {
        __sincosf(x[k].x, &S0[k], &C0[k]);
        __sincosf(x[k].y, &S1[k], &C1[k]);
        __sincosf(x[k].z, &S2[k], &C2[k]);
    }

    cudaGridDependencySynchronize();

    __shared__ float cs[27];
    if (threadIdx.x < 27) cs[threadIdx.x] = d_C[threadIdx.x];
    __syncthreads();

    #pragma unroll
    for (int k = 0; k < SPT; k++) {
        float u0[3] = {1.f, C0[k], S0[k]};
        float u1[3] = {1.f, C1[k], S1[k]};
        float z = 0.f;
        #pragma unroll
        for (int p = 0; p < 3; p++) {
            #pragma unroll
            for (int q = 0; q < 3; q++) {
                const float* c3 = &cs[p * 9 + q * 3];
                float w = c3[0];
                w = fmaf(c3[1], C2[k], w);
                w = fmaf(c3[2], S2[k], w);
                z = fmaf(u0[p] * u1[q], w, z);
            }
        }
        int i = t + k * T;
        if (i < B) out[i] = z;
    }
}

extern "C" void kernel_launch(void* const* d_in, const int* in_sizes, int n_in,
                              void* d_out, int out_size) {
    const float* inputs = (const float*)d_in[0];   // (B, 8) float32
    const float* qw     = (const float*)d_in[1];   // (3, 3, 2) float32
    float* out          = (float*)d_out;           // (B, 1) float32

    int B = in_sizes[0] / 8;

    build_coeffs<<<1, 32>>>(qw);

    int grid = (B + BLOCK * SPT - 1) / (BLOCK * SPT);   // 512 for B = 2^20

    cudaLaunchConfig_t cfg = {};
    cfg.gridDim = dim3(grid);
    cfg.blockDim = dim3(BLOCK);
    cfg.dynamicSmemBytes = 0;
    cudaLaunchAttribute attr[1];
    attr[0].id = cudaLaunchAttributeProgrammaticStreamSerialization;
    attr[0].val.programmaticStreamSerializationAllowed = 1;
    cfg.attrs = attr;
    cfg.numAttrs = 1;

    cudaLaunchKernelEx(&cfg, vqc_eval, (const float4*)inputs, out, B);
}

// round 13
// speedup vs baseline: 1.1910x; 1.0209x over previous
#include <cuda_runtime.h>
#include <cstdint>

// z = sum_{p,q,r} C[p*9+q*3+r] * u0_p * u1_q * u2_r,  u_i = (1, cos x_i, sin x_i)
__device__ float d_C[27];

// ---------------------------------------------------------------------------
// Kernel 1: build the 27 trilinear coefficients from q_weights (18 floats).
// Single warp, no block barriers; all 18 sincos in parallel up front.
// ---------------------------------------------------------------------------
__global__ void build_coeffs(const float* __restrict__ qw) {
    __shared__ float Ure[8][8];   // [m][j]
    __shared__ float Uim[8][8];
    __shared__ float Aj[8][8];    // A[j][k]

    const unsigned FULL = 0xFFFFFFFFu;
    const int lane = threadIdx.x;

    float ang = (lane < 18) ? 0.5f * qw[lane] : 0.f;
    float sh, ch;
    __sincosf(ang, &sh, &ch);

    const int j = lane & 7;
    float sr[8], si[8];
    #pragma unroll
    for (int m = 0; m < 8; m++) { sr[m] = 0.f; si[m] = 0.f; }
    sr[j] = 1.0f;

    #pragma unroll
    for (int g = 0; g < 9; g++) {          // layer = g/3, qubit = g%3
        const int bit = 4 >> (g % 3);
        float cy = __shfl_sync(FULL, ch, 2 * g);
        float sy = __shfl_sync(FULL, sh, 2 * g);
        float cz = __shfl_sync(FULL, ch, 2 * g + 1);
        float sz = __shfl_sync(FULL, sh, 2 * g + 1);

        #pragma unroll
        for (int m = 0; m < 8; m++) {      // RY
            if (m & bit) continue;
            int m1 = m | bit;
            float ar = sr[m],  ai = si[m];
            float br = sr[m1], bi = si[m1];
            sr[m]  = cy * ar - sy * br;  si[m]  = cy * ai - sy * bi;
            sr[m1] = sy * ar + cy * br;  si[m1] = sy * ai + cy * bi;
        }
        #pragma unroll
        for (int m = 0; m < 8; m++) {      // RZ
            float ar = sr[m], ai = si[m];
            if (m & bit) { sr[m] = cz * ar - sz * ai; si[m] = cz * ai + sz * ar; }
            else         { sr[m] = cz * ar + sz * ai; si[m] = cz * ai - sz * ar; }
        }
        if (g % 3 == 2) {
            #pragma unroll
            for (int m = 4; m < 6; m++) {  // CNOT01: swap (4,6),(5,7)
                int m1 = m | 2; float tmp;
                tmp = sr[m]; sr[m] = sr[m1]; sr[m1] = tmp;
                tmp = si[m]; si[m] = si[m1]; si[m1] = tmp;
            }
            #pragma unroll
            for (int m = 2; m < 8; m += 4) { // CNOT12: swap (2,3),(6,7)
                int m1 = m | 1; float tmp;
                tmp = sr[m]; sr[m] = sr[m1]; sr[m1] = tmp;
                tmp = si[m]; si[m] = si[m1]; si[m1] = tmp;
            }
        }
    }

    if (lane < 8) {
        #pragma unroll
        for (int m = 0; m < 8; m++) { Ure[m][j] = sr[m]; Uim[m][j] = si[m]; }
    }
    __syncwarp();

    #pragma unroll
    for (int h = 0; h < 2; h++) {
        int e = lane + h * 32;
        int jj = e >> 3, kk = e & 7;
        float a = 0.f;
        #pragma unroll
        for (int m = 0; m < 8; m++) {
            float sgn = (m & 4) ? -1.f : 1.f;
            a += sgn * (Ure[m][jj] * Ure[m][kk] + Uim[m][jj] * Uim[m][kk]);
        }
        Aj[jj][kk] = a;
    }
    __syncwarp();

    float cpart[27];
    #pragma unroll
    for (int i = 0; i < 27; i++) cpart[i] = 0.f;

    #pragma unroll
    for (int h = 0; h < 2; h++) {
        int e = lane + h * 32;
        int jj = e >> 3, kk = e & 7;
        float a = Aj[jj][kk];

        float ga[3], gb[3], gc[3];
        {
            int aa = (jj >> 2) & 1, bb = (kk >> 2) & 1;
            ga[0] = (aa == bb) ? 0.5f : 0.f;
            ga[1] = (aa == bb) ? (aa ? -0.5f : 0.5f) : 0.f;
            ga[2] = (aa != bb) ? 0.5f : 0.f;
        }
        {
            int aa = (jj >> 1) & 1, bb = (kk >> 1) & 1;
            gb[0] = (aa == bb) ? 0.5f : 0.f;
            gb[1] = (aa == bb) ? (aa ? -0.5f : 0.5f) : 0.f;
            gb[2] = (aa != bb) ? 0.5f : 0.f;
        }
        {
            int aa = jj & 1, bb = kk & 1;
            gc[0] = (aa == bb) ? 0.5f : 0.f;
            gc[1] = (aa == bb) ? (aa ? -0.5f : 0.5f) : 0.f;
            gc[2] = (aa != bb) ? 0.5f : 0.f;
        }

        #pragma unroll
        for (int p = 0; p < 3; p++) {
            float a0 = a * ga[p];
            #pragma unroll
            for (int q = 0; q < 3; q++) {
                float a01 = a0 * gb[q];
                #pragma unroll
                for (int r = 0; r < 3; r++)
                    cpart[p * 9 + q * 3 + r] =
                        fmaf(a01, gc[r], cpart[p * 9 + q * 3 + r]);
            }
        }
    }

    #pragma unroll
    for (int off = 16; off > 0; off >>= 1) {
        #pragma unroll
        for (int i = 0; i < 27; i++)
            cpart[i] += __shfl_xor_sync(FULL, cpart[i], off);
    }
    if (lane < 27) d_C[lane] = cpart[lane];
}

// ---------------------------------------------------------------------------
// Kernel 2 (PDL): loads -> ALL sincos -> grid-dependency sync -> trilinear.
// Everything before the sync is independent of build_coeffs, so its whole
// execution (plus the DRAM latency of the loads) overlaps the build.
// ---------------------------------------------------------------------------
static constexpr int SPT = 8;
static constexpr int BLOCK = 256;

__global__ void __launch_bounds__(BLOCK) vqc_eval(const float4* __restrict__ in,
                                                  float* __restrict__ out, int B) {
    const int T = gridDim.x * BLOCK;
    const int t = blockIdx.x * BLOCK + threadIdx.x;

    // Front-batch ALL loads.
    float4 x[SPT];
    #pragma unroll
    for (int k = 0; k < SPT; k++) {
        int i = t + k * T;
        i = (i < B) ? i : (B - 1);
        x[k] = in[(size_t)i * 2];     // first 16B of the 32B row
    }

    // All trig BEFORE the dependency sync — overlaps build_coeffs.
    float C0[SPT], S0[SPT], C1[SPT], S1[SPT], C2[SPT], S2[SPT];
    #pragma unroll
    for (int k = 0; k < SPT; k++) {
        __sincosf(x[k].x, &S0[k], &C0[k]);
        __sincosf(x[k].y, &S1[k], &C1[k]);
        __sincosf(x[k].z, &S2[k], &C2[k]);
    }

    cudaGridDependencySynchronize();

    __shared__ float cs[27];
    if (threadIdx.x < 27) cs[threadIdx.x] = d_C[threadIdx.x];
    __syncthreads();

    #pragma unroll
    for (int k = 0; k < SPT; k++) {
        float u0[3] = {1.f, C0[k], S0[k]};
        float u1[3] = {1.f, C1[k], S1[k]};
        float z = 0.f;
        #pragma unroll
        for (int p = 0; p < 3; p++) {
            #pragma unroll
            for (int q = 0; q < 3; q++) {
                const float* c3 = &cs[p * 9 + q * 3];
                float w = c3[0];
                w = fmaf(c3[1], C2[k], w);
                w = fmaf(c3[2], S2[k], w);
                z = fmaf(u0[p] * u1[q], w, z);
            }
        }
        int i = t + k * T;
        if (i < B) out[i] = z;
    }
}

extern "C" void kernel_launch(void* const* d_in, const int* in_sizes, int n_in,
                              void* d_out, int out_size) {
    const float* inputs = (const float*)d_in[0];   // (B, 8) float32
    const float* qw     = (const float*)d_in[1];   // (3, 3, 2) float32
    float* out          = (float*)d_out;           // (B, 1) float32

    int B = in_sizes[0] / 8;

    build_coeffs<<<1, 32>>>(qw);

    int grid = (B + BLOCK * SPT - 1) / (BLOCK * SPT);   // 512 for B = 2^20

    cudaLaunchConfig_t cfg = {};
    cfg.gridDim = dim3(grid);
    cfg.blockDim = dim3(BLOCK);
    cfg.dynamicSmemBytes = 0;
    cudaLaunchAttribute attr[1];
    attr[0].id = cudaLaunchAttributeProgrammaticStreamSerialization;
    attr[0].val.programmaticStreamSerializationAllowed = 1;
    cfg.attrs = attr;
    cfg.numAttrs = 1;

    cudaLaunchKernelEx(&cfg, vqc_eval, (const float4*)inputs, out, B);
}